// round 1
// baseline (speedup 1.0000x reference)
#include <cuda_runtime.h>
#include <math.h>

#define Bk   8
#define Cc   512
#define Wd   64
#define Hd   32
#define HIDd 256
#define Gg   1280
#define WH   (Wd*Hd)        // 2048
#define MXP  (Bk*WH)        // 16384

// ---------------- device scratch (no allocations allowed) ----------------
__device__ float g_xp[(size_t)MXP * Gg];            // 16384*1280  (~84 MB)
__device__ float g_h [(size_t)WH * Bk * HIDd];      // (w,h,b,hid)
__device__ float g_c [(size_t)WH * Bk * HIDd];
__device__ float g_gs[(size_t)256 * Gg];            // per-diagonal gate scratch (recurrent part)
__device__ float g_part[2 * 128 * HIDd];            // partial sums for BN
__device__ float g_scale[HIDd];
__device__ float g_shift[HIDd];

// ---------------- Kernel A: xp = x @ Wx + b ----------------
// A row m = b*2048 + (w*H + h); A[m][c] = x[b][c][wh] (coalesced over m).
// Tiles: BM=128, BN=64, BK=16, 256 threads, 8x4 per thread.
__global__ __launch_bounds__(256) void xp_gemm(const float* __restrict__ x,
                                               const float* __restrict__ Wx,
                                               const float* __restrict__ bias) {
    __shared__ float As[16][128];
    __shared__ float Bs[16][64];
    const int bm  = blockIdx.y * 128;
    const int bn  = blockIdx.x * 64;
    const int tid = threadIdx.x;

    const int b   = bm >> 11;          // 2048 rows per batch element; 128 | 2048
    const int wh0 = bm & 2047;
    const float* xb = x + (size_t)b * Cc * WH + wh0;

    const int am  = tid & 127;         // m within tile (A load)
    const int ak  = tid >> 7;          // 0..1
    const int bkr = tid >> 4;          // 0..15 (B load row)
    const int bn4 = (tid & 15) * 4;
    const int tx  = tid & 15;          // 16 col groups * 4
    const int ty  = tid >> 4;          // 16 row groups * 8

    float acc[8][4];
#pragma unroll
    for (int i = 0; i < 8; i++)
#pragma unroll
        for (int j = 0; j < 4; j++) acc[i][j] = 0.f;

    for (int k0 = 0; k0 < Cc; k0 += 16) {
#pragma unroll
        for (int j = 0; j < 8; j++) {
            int c = ak + j * 2;
            As[c][am] = xb[(size_t)(k0 + c) * WH + am];
        }
        *(float4*)&Bs[bkr][bn4] =
            *(const float4*)&Wx[(size_t)(k0 + bkr) * Gg + bn + bn4];
        __syncthreads();
#pragma unroll
        for (int kk = 0; kk < 16; kk++) {
            float4 a0 = *(float4*)&As[kk][ty * 8];
            float4 a1 = *(float4*)&As[kk][ty * 8 + 4];
            float4 bv = *(float4*)&Bs[kk][tx * 4];
            float aa[8] = {a0.x, a0.y, a0.z, a0.w, a1.x, a1.y, a1.z, a1.w};
            float bb[4] = {bv.x, bv.y, bv.z, bv.w};
#pragma unroll
            for (int i = 0; i < 8; i++)
#pragma unroll
                for (int j = 0; j < 4; j++) acc[i][j] += aa[i] * bb[j];
        }
        __syncthreads();
    }

    float4 bb4 = *(const float4*)&bias[bn + tx * 4];
#pragma unroll
    for (int i = 0; i < 8; i++) {
        int m = bm + ty * 8 + i;
        float4 v;
        v.x = acc[i][0] + bb4.x;
        v.y = acc[i][1] + bb4.y;
        v.z = acc[i][2] + bb4.z;
        v.w = acc[i][3] + bb4.w;
        *(float4*)&g_xp[(size_t)m * Gg + bn + tx * 4] = v;
    }
}

// ---------------- Kernel G: per-diagonal recurrent GEMM ----------------
// g_gs[m][g] = h_left(m) @ Wh1 + h_up(m) @ Wh2, m = cell_idx*8 + b (M rows).
// K = 512 (first 256 -> left neighbor with Wh1, last 256 -> up neighbor with Wh2).
// Tiles: BM=32, BN=64, BK=16, 256 threads, 2x4 per thread.
__global__ __launch_bounds__(256) void diag_gemm(int d, int w_lo, int M,
                                                 const float* __restrict__ Wh1,
                                                 const float* __restrict__ Wh2) {
    __shared__ float As[16][33];
    __shared__ float Bs[16][64];
    const int bm  = blockIdx.y * 32;
    const int bn  = blockIdx.x * 64;
    const int tid = threadIdx.x;

    // A-load mapping: 8 lanes per row cover 16 consecutive k (float2 each)
    const int arow = tid >> 3;          // 0..31
    const int akq  = (tid & 7) * 2;     // 0,2,...,14

    const float* pl = nullptr;          // left neighbor row base (k 0..255)
    const float* pu = nullptr;          // up   neighbor row base (k 256..511)
    {
        int m = bm + arow;
        if (m < M) {
            int ci = m >> 3, b = m & 7;
            int w = w_lo + ci, h = d - w;
            if (h > 0) pl = g_h + ((size_t)((w * Hd + (h - 1)) * Bk + b)) * HIDd;
            if (w > 0) pu = g_h + ((size_t)(((w - 1) * Hd + h) * Bk + b)) * HIDd;
        }
    }

    const int bkr = tid >> 4;           // 0..15
    const int bn4 = (tid & 15) * 4;
    const int tx  = tid & 15;           // *4 cols
    const int ty  = tid >> 4;           // *2 rows

    float acc[2][4];
#pragma unroll
    for (int i = 0; i < 2; i++)
#pragma unroll
        for (int j = 0; j < 4; j++) acc[i][j] = 0.f;

    for (int k0 = 0; k0 < 2 * HIDd; k0 += 16) {
        const float* src;
        const float* Wsrc;
        int koff;
        if (k0 < HIDd) { src = pl; koff = k0;        Wsrc = Wh1 + (size_t)k0 * Gg; }
        else           { src = pu; koff = k0 - HIDd; Wsrc = Wh2 + (size_t)(k0 - HIDd) * Gg; }

        float2 v = make_float2(0.f, 0.f);
        if (src) v = *(const float2*)&src[koff + akq];
        As[akq][arow]     = v.x;
        As[akq + 1][arow] = v.y;
        *(float4*)&Bs[bkr][bn4] =
            *(const float4*)&Wsrc[(size_t)bkr * Gg + bn + bn4];
        __syncthreads();
#pragma unroll
        for (int kk = 0; kk < 16; kk++) {
            float a0 = As[kk][ty * 2];
            float a1 = As[kk][ty * 2 + 1];
            float4 bv = *(float4*)&Bs[kk][tx * 4];
            acc[0][0] += a0 * bv.x; acc[0][1] += a0 * bv.y;
            acc[0][2] += a0 * bv.z; acc[0][3] += a0 * bv.w;
            acc[1][0] += a1 * bv.x; acc[1][1] += a1 * bv.y;
            acc[1][2] += a1 * bv.z; acc[1][3] += a1 * bv.w;
        }
        __syncthreads();
    }
#pragma unroll
    for (int i = 0; i < 2; i++) {
        int mm = bm + ty * 2 + i;
        if (mm < M) {
            float4 v = make_float4(acc[i][0], acc[i][1], acc[i][2], acc[i][3]);
            *(float4*)&g_gs[(size_t)mm * Gg + bn + tx * 4] = v;
        }
    }
}

// ---------------- Kernel P: per-diagonal gate pointwise ----------------
__global__ __launch_bounds__(256) void pointwise(int d, int w_lo) {
    const int m = blockIdx.x;           // 0..M-1
    const int j = threadIdx.x;          // hid
    const int ci = m >> 3, b = m & 7;
    const int w = w_lo + ci, h = d - w;

    const float* gg = g_gs + (size_t)m * Gg;
    const float* xg = g_xp + ((size_t)(b * WH + w * Hd + h)) * Gg;

    float gi  = xg[j]            + gg[j];
    float gf1 = xg[HIDd + j]     + gg[HIDd + j];
    float gf2 = xg[2 * HIDd + j] + gg[2 * HIDd + j];
    float go  = xg[3 * HIDd + j] + gg[3 * HIDd + j];
    float gc  = xg[4 * HIDd + j] + gg[4 * HIDd + j];

    float i_ = 1.f / (1.f + expf(-gi));
    float f1 = 1.f / (1.f + expf(-gf1));
    float f2 = 1.f / (1.f + expf(-gf2));
    float o_ = 1.f / (1.f + expf(-go));
    float cand = tanhf(gc);

    float cl = (h > 0) ? g_c[((size_t)((w * Hd + (h - 1)) * Bk + b)) * HIDd + j] : 0.f;
    float cu = (w > 0) ? g_c[((size_t)(((w - 1) * Hd + h) * Bk + b)) * HIDd + j] : 0.f;

    float c  = i_ * cand + f1 * cl + f2 * cu;
    float hv = o_ * tanhf(c);

    size_t oidx = ((size_t)((w * Hd + h) * Bk + b)) * HIDd + j;
    g_c[oidx] = c;
    g_h[oidx] = hv;
}

// ---------------- BN stats (deterministic, no float atomics) ----------------
__global__ __launch_bounds__(256) void bn_reduce1() {
    const int t = threadIdx.x;          // channel
    const size_t r0 = (size_t)blockIdx.x * 128;
    float s = 0.f, s2 = 0.f;
    for (int r = 0; r < 128; r++) {
        float v = g_h[(r0 + r) * HIDd + t];
        s += v;
        s2 += v * v;
    }
    g_part[blockIdx.x * HIDd + t] = s;
    g_part[128 * HIDd + blockIdx.x * HIDd + t] = s2;
}

__global__ __launch_bounds__(256) void bn_reduce2(const float* __restrict__ gamma,
                                                  const float* __restrict__ beta) {
    const int t = threadIdx.x;
    float s = 0.f, s2 = 0.f;
    for (int i = 0; i < 128; i++) {
        s += g_part[i * HIDd + t];
        s2 += g_part[128 * HIDd + i * HIDd + t];
    }
    const float invn = 1.f / (float)MXP;
    float mean = s * invn;
    float var  = s2 * invn - mean * mean;
    float sc   = gamma[t] * rsqrtf(var + 1e-5f);
    g_scale[t] = sc;
    g_shift[t] = beta[t] - mean * sc;
}

// ---------------- final writeout: out | state | cell, layout (B,HID,W,H) ----------------
__global__ __launch_bounds__(256) void writeout(float* __restrict__ out) {
    size_t idx = (size_t)blockIdx.x * 256 + threadIdx.x;   // 0 .. 4194303
    int hh = (int)(idx & 31);
    int w  = (int)((idx >> 5) & 63);
    int ch = (int)((idx >> 11) & 255);
    int b  = (int)(idx >> 19);
    size_t src = ((size_t)((w * Hd + hh) * Bk + b)) * HIDd + ch;
    float st = g_h[src];
    float cc = g_c[src];
    out[idx]                      = tanhf(st * g_scale[ch] + g_shift[ch]);
    out[(size_t)MXP * HIDd + idx]     = st;   // state
    out[(size_t)2 * MXP * HIDd + idx] = cc;   // cell
}

// ---------------- launch ----------------
extern "C" void kernel_launch(void* const* d_in, const int* in_sizes, int n_in,
                              void* d_out, int out_size) {
    const float* x     = (const float*)d_in[0];
    const float* Wx    = (const float*)d_in[1];
    const float* Wh1   = (const float*)d_in[2];
    const float* Wh2   = (const float*)d_in[3];
    const float* bias  = (const float*)d_in[4];
    const float* gamma = (const float*)d_in[5];
    const float* beta  = (const float*)d_in[6];
    float* out = (float*)d_out;

    xp_gemm<<<dim3(Gg / 64, MXP / 128), 256>>>(x, Wx, bias);

    for (int d = 0; d < Wd + Hd - 1; d++) {
        int w_lo = d - (Hd - 1); if (w_lo < 0) w_lo = 0;
        int w_hi = (d < Wd - 1) ? d : (Wd - 1);
        int nc = w_hi - w_lo + 1;
        int M = nc * Bk;
        diag_gemm<<<dim3(Gg / 64, (M + 31) / 32), 256>>>(d, w_lo, M, Wh1, Wh2);
        pointwise<<<M, 256>>>(d, w_lo);
    }

    bn_reduce1<<<128, 256>>>();
    bn_reduce2<<<1, 256>>>(gamma, beta);
    writeout<<<MXP, 256>>>(out);
}

// round 3
// speedup vs baseline: 1.2774x; 1.2774x over previous
#include <cuda_runtime.h>
#include <math.h>

#define Bk   8
#define Cc   512
#define Wd   64
#define Hd   32
#define HIDd 256
#define Gg   1280
#define WH   (Wd*Hd)        // 2048
#define MXP  (Bk*WH)        // 16384

// ---------------- device scratch (no allocations allowed) ----------------
__device__ float g_xp[(size_t)MXP * Gg];            // input projection (b, w*H+h) x G
__device__ float g_h [(size_t)WH * Bk * HIDd];      // (w,h,b,hid)
__device__ float g_c [(size_t)WH * Bk * HIDd];
__device__ float g_part[2 * 128 * HIDd];            // partial sums for BN
__device__ float g_scale[HIDd];
__device__ float g_shift[HIDd];

// ---------------- Kernel A: xp = x @ Wx + b (unchanged; near fp32 floor) ----------------
__global__ __launch_bounds__(256) void xp_gemm(const float* __restrict__ x,
                                               const float* __restrict__ Wx,
                                               const float* __restrict__ bias) {
    __shared__ float As[16][128];
    __shared__ float Bs[16][64];
    const int bm  = blockIdx.y * 128;
    const int bn  = blockIdx.x * 64;
    const int tid = threadIdx.x;

    const int b   = bm >> 11;
    const int wh0 = bm & 2047;
    const float* xb = x + (size_t)b * Cc * WH + wh0;

    const int am  = tid & 127;
    const int ak  = tid >> 7;
    const int bkr = tid >> 4;
    const int bn4 = (tid & 15) * 4;
    const int tx  = tid & 15;
    const int ty  = tid >> 4;

    float acc[8][4];
#pragma unroll
    for (int i = 0; i < 8; i++)
#pragma unroll
        for (int j = 0; j < 4; j++) acc[i][j] = 0.f;

    for (int k0 = 0; k0 < Cc; k0 += 16) {
#pragma unroll
        for (int j = 0; j < 8; j++) {
            int c = ak + j * 2;
            As[c][am] = xb[(size_t)(k0 + c) * WH + am];
        }
        *(float4*)&Bs[bkr][bn4] =
            *(const float4*)&Wx[(size_t)(k0 + bkr) * Gg + bn + bn4];
        __syncthreads();
#pragma unroll
        for (int kk = 0; kk < 16; kk++) {
            float4 a0 = *(float4*)&As[kk][ty * 8];
            float4 a1 = *(float4*)&As[kk][ty * 8 + 4];
            float4 bv = *(float4*)&Bs[kk][tx * 4];
            float aa[8] = {a0.x, a0.y, a0.z, a0.w, a1.x, a1.y, a1.z, a1.w};
            float bb[4] = {bv.x, bv.y, bv.z, bv.w};
#pragma unroll
            for (int i = 0; i < 8; i++)
#pragma unroll
                for (int j = 0; j < 4; j++) acc[i][j] += aa[i] * bb[j];
        }
        __syncthreads();
    }

    float4 bb4 = *(const float4*)&bias[bn + tx * 4];
#pragma unroll
    for (int i = 0; i < 8; i++) {
        int m = bm + ty * 8 + i;
        float4 v;
        v.x = acc[i][0] + bb4.x;
        v.y = acc[i][1] + bb4.y;
        v.z = acc[i][2] + bb4.z;
        v.w = acc[i][3] + bb4.w;
        *(float4*)&g_xp[(size_t)m * Gg + bn + tx * 4] = v;
    }
}

// ---------------- Kernel D: fused diagonal step (recurrent GEMM + LSTM pointwise) ----------------
// Block (nb, by): nb = hid chunk of 32 (gate cols = g*256 + nb*32 + t, g=0..4),
//                 by = row chunk: rows [by*mt, by*mt+mt), mt = ceil(M/16) (<=16).
// K = 512: k<256 -> left-neighbor h @ Wh1 ; k>=256 -> up-neighbor h @ Wh2.
// 256 threads: tn = tid&31 (hid within chunk), tm = tid>>5 (2 row slots each).
// Accumulates full K in-block, then computes gates/cell/state in registers.
__global__ __launch_bounds__(256) void diag_step(int d, int w_lo, int M, int mt,
                                                 const float* __restrict__ Wh1,
                                                 const float* __restrict__ Wh2) {
    __shared__ float Bs[32][160];
    __shared__ float As[32][18];
    __shared__ const float* pls[16];   // left-neighbor h row base (or null)
    __shared__ const float* pus[16];   // up-neighbor   h row base (or null)

    const int tid = threadIdx.x;
    const int nb  = blockIdx.x;        // 0..7
    const int by  = blockIdx.y;        // 0..15
    const int r0  = by * mt;           // first global row of this block
    if (r0 >= M) return;

    // row -> neighbor pointers (computed once)
    if (tid < 16) {
        const float* pl = nullptr;
        const float* pu = nullptr;
        int gr = r0 + tid;
        if (tid < mt && gr < M) {
            int ci = gr >> 3, b = gr & 7;
            int w = w_lo + ci, h = d - w;
            if (h > 0) pl = g_h + ((size_t)((w * Hd + (h - 1)) * Bk + b)) * HIDd;
            if (w > 0) pu = g_h + ((size_t)(((w - 1) * Hd + h) * Bk + b)) * HIDd;
        }
        pls[tid] = pl;
        pus[tid] = pu;
    }
    __syncthreads();

    const int tn = tid & 31;
    const int tm = tid >> 5;           // 0..7, rows 2tm, 2tm+1 (local)

    float acc[2][5];
#pragma unroll
    for (int i = 0; i < 2; i++)
#pragma unroll
        for (int g = 0; g < 5; g++) acc[i][g] = 0.f;

    // B-load mapping (5 float4 per thread per step)
    int bkk[5], bg[5], bt4[5];
#pragma unroll
    for (int j = 0; j < 5; j++) {
        int i  = tid + j * 256;        // 0..1279
        bkk[j] = i / 40;
        int c4 = i % 40;
        bg[j]  = c4 >> 3;
        bt4[j] = (c4 & 7) << 2;
    }
    // A-load mapping (2 scalars per thread per step)
    const int arow0 = tid >> 5;        // 0..7
    const int arow1 = (tid + 256) >> 5;// 8..15
    const int akk   = tid & 31;

    float4 breg[5];
    float  areg[2];

    // ---- prologue: load step 0 ----
    {
        const float* Wsrc = Wh1;       // k0 = 0
#pragma unroll
        for (int j = 0; j < 5; j++)
            breg[j] = *(const float4*)&Wsrc[(size_t)bkk[j] * Gg + bg[j] * HIDd + nb * 32 + bt4[j]];
        const float* p0 = pls[arow0];
        const float* p1 = pls[arow1];
        areg[0] = p0 ? p0[akk] : 0.f;
        areg[1] = p1 ? p1[akk] : 0.f;
    }

    for (int s = 0; s < 16; s++) {
        __syncthreads();
        // store prefetched tile
#pragma unroll
        for (int j = 0; j < 5; j++)
            *(float4*)&Bs[bkk[j]][(bg[j] << 5) + bt4[j]] = breg[j];
        As[akk][arow0] = areg[0];
        As[akk][arow1] = areg[1];
        __syncthreads();

        // issue loads for next step (latency hidden under compute)
        if (s + 1 < 16) {
            int k0 = (s + 1) * 32;
            const float* Wsrc;
            const float* const* P;
            int koff;
            if (k0 < HIDd) { Wsrc = Wh1 + (size_t)k0 * Gg; P = pls; koff = k0; }
            else           { Wsrc = Wh2 + (size_t)(k0 - HIDd) * Gg; P = pus; koff = k0 - HIDd; }
#pragma unroll
            for (int j = 0; j < 5; j++)
                breg[j] = *(const float4*)&Wsrc[(size_t)bkk[j] * Gg + bg[j] * HIDd + nb * 32 + bt4[j]];
            const float* p0 = P[arow0];
            const float* p1 = P[arow1];
            areg[0] = p0 ? p0[koff + akk] : 0.f;
            areg[1] = p1 ? p1[koff + akk] : 0.f;
        }

        // compute current tile
#pragma unroll
        for (int kk = 0; kk < 32; kk++) {
            float2 a = *(const float2*)&As[kk][tm * 2];
            float b0 = Bs[kk][tn];
            float b1 = Bs[kk][32 + tn];
            float b2 = Bs[kk][64 + tn];
            float b3 = Bs[kk][96 + tn];
            float b4 = Bs[kk][128 + tn];
            acc[0][0] += a.x * b0; acc[0][1] += a.x * b1; acc[0][2] += a.x * b2;
            acc[0][3] += a.x * b3; acc[0][4] += a.x * b4;
            acc[1][0] += a.y * b0; acc[1][1] += a.y * b1; acc[1][2] += a.y * b2;
            acc[1][3] += a.y * b3; acc[1][4] += a.y * b4;
        }
    }

    // ---- fused LSTM pointwise ----
    const int hid = nb * 32 + tn;
#pragma unroll
    for (int i = 0; i < 2; i++) {
        int lr = tm * 2 + i;
        int gr = r0 + lr;
        if (lr < mt && gr < M) {
            int ci = gr >> 3, b = gr & 7;
            int w = w_lo + ci, h = d - w;

            const float* xg = g_xp + ((size_t)(b * WH + w * Hd + h)) * Gg;
            float gi  = acc[i][0] + xg[hid];
            float gf1 = acc[i][1] + xg[HIDd + hid];
            float gf2 = acc[i][2] + xg[2 * HIDd + hid];
            float go  = acc[i][3] + xg[3 * HIDd + hid];
            float gc  = acc[i][4] + xg[4 * HIDd + hid];

            float i_ = 1.f / (1.f + expf(-gi));
            float f1 = 1.f / (1.f + expf(-gf1));
            float f2 = 1.f / (1.f + expf(-gf2));
            float o_ = 1.f / (1.f + expf(-go));
            float cand = tanhf(gc);

            float cl = (h > 0) ? g_c[((size_t)((w * Hd + (h - 1)) * Bk + b)) * HIDd + hid] : 0.f;
            float cu = (w > 0) ? g_c[((size_t)(((w - 1) * Hd + h) * Bk + b)) * HIDd + hid] : 0.f;

            float c  = i_ * cand + f1 * cl + f2 * cu;
            float hv = o_ * tanhf(c);

            size_t oidx = ((size_t)((w * Hd + h) * Bk + b)) * HIDd + hid;
            g_c[oidx] = c;
            g_h[oidx] = hv;
        }
    }
}

// ---------------- BN stats (deterministic, no float atomics) ----------------
__global__ __launch_bounds__(256) void bn_reduce1() {
    const int t = threadIdx.x;
    const size_t r0 = (size_t)blockIdx.x * 128;
    float s = 0.f, s2 = 0.f;
    for (int r = 0; r < 128; r++) {
        float v = g_h[(r0 + r) * HIDd + t];
        s += v;
        s2 += v * v;
    }
    g_part[blockIdx.x * HIDd + t] = s;
    g_part[128 * HIDd + blockIdx.x * HIDd + t] = s2;
}

__global__ __launch_bounds__(256) void bn_reduce2(const float* __restrict__ gamma,
                                                  const float* __restrict__ beta) {
    const int t = threadIdx.x;
    float s = 0.f, s2 = 0.f;
    for (int i = 0; i < 128; i++) {
        s += g_part[i * HIDd + t];
        s2 += g_part[128 * HIDd + i * HIDd + t];
    }
    const float invn = 1.f / (float)MXP;
    float mean = s * invn;
    float var  = s2 * invn - mean * mean;
    float sc   = gamma[t] * rsqrtf(var + 1e-5f);
    g_scale[t] = sc;
    g_shift[t] = beta[t] - mean * sc;
}

// ---------------- final writeout: out | state | cell, layout (B,HID,W,H) ----------------
__global__ __launch_bounds__(256) void writeout(float* __restrict__ out) {
    size_t idx = (size_t)blockIdx.x * 256 + threadIdx.x;
    int hh = (int)(idx & 31);
    int w  = (int)((idx >> 5) & 63);
    int ch = (int)((idx >> 11) & 255);
    int b  = (int)(idx >> 19);
    size_t src = ((size_t)((w * Hd + hh) * Bk + b)) * HIDd + ch;
    float st = g_h[src];
    float cc = g_c[src];
    out[idx]                          = tanhf(st * g_scale[ch] + g_shift[ch]);
    out[(size_t)MXP * HIDd + idx]     = st;
    out[(size_t)2 * MXP * HIDd + idx] = cc;
}

// ---------------- launch ----------------
extern "C" void kernel_launch(void* const* d_in, const int* in_sizes, int n_in,
                              void* d_out, int out_size) {
    const float* x     = (const float*)d_in[0];
    const float* Wx    = (const float*)d_in[1];
    const float* Wh1   = (const float*)d_in[2];
    const float* Wh2   = (const float*)d_in[3];
    const float* bias  = (const float*)d_in[4];
    const float* gamma = (const float*)d_in[5];
    const float* beta  = (const float*)d_in[6];
    float* out = (float*)d_out;

    xp_gemm<<<dim3(Gg / 64, MXP / 128), 256>>>(x, Wx, bias);

    for (int d = 0; d < Wd + Hd - 1; d++) {
        int w_lo = d - (Hd - 1); if (w_lo < 0) w_lo = 0;
        int w_hi = (d < Wd - 1) ? d : (Wd - 1);
        int nc = w_hi - w_lo + 1;
        int M = nc * Bk;
        int mt = (M + 15) / 16;
        diag_step<<<dim3(8, 16), 256>>>(d, w_lo, M, mt, Wh1, Wh2);
    }

    bn_reduce1<<<128, 256>>>();
    bn_reduce2<<<1, 256>>>(gamma, beta);
    writeout<<<MXP, 256>>>(out);
}

// round 4
// speedup vs baseline: 1.6235x; 1.2709x over previous
#include <cuda_runtime.h>
#include <math.h>

#define Bk   8
#define Cc   512
#define Wd   64
#define Hd   32
#define HIDd 256
#define Gg   1280
#define WH   (Wd*Hd)        // 2048
#define MXP  (Bk*WH)        // 16384
#define NDIAG (Wd + Hd - 1) // 95
#define NBLK 144            // 16 hid-chunks x 9 row-groups, all co-resident (<=148 SMs)
#define RG   9

// smem layout (floats): Ws[512][80] | As[2][64][34] | ptrs
#define WS_FLOATS (512*80)          // 40960
#define AS_PITCH  34
#define AS_BUF    (64*AS_PITCH)     // 2176
#define AS_FLOATS (2*AS_BUF)        // 4352
#define SMEM_BYTES ((WS_FLOATS + AS_FLOATS)*4 + 64*8)

// ---------------- device scratch ----------------
__device__ float g_xp[(size_t)MXP * Gg];
__device__ float g_h [(size_t)WH * Bk * HIDd];      // (w,h,b,hid)
__device__ float g_c [(size_t)WH * Bk * HIDd];
__device__ float g_part[2 * 128 * HIDd];
__device__ float g_scale[HIDd];
__device__ float g_shift[HIDd];
__device__ unsigned g_cnt = 0;
__device__ unsigned g_gen = 0;

// ---------------- Kernel A: xp = x @ Wx + b ----------------
__global__ __launch_bounds__(256) void xp_gemm(const float* __restrict__ x,
                                               const float* __restrict__ Wx,
                                               const float* __restrict__ bias) {
    __shared__ float As[16][128];
    __shared__ float Bs[16][64];
    const int bm  = blockIdx.y * 128;
    const int bn  = blockIdx.x * 64;
    const int tid = threadIdx.x;

    const int b   = bm >> 11;
    const int wh0 = bm & 2047;
    const float* xb = x + (size_t)b * Cc * WH + wh0;

    const int am  = tid & 127;
    const int ak  = tid >> 7;
    const int bkr = tid >> 4;
    const int bn4 = (tid & 15) * 4;
    const int tx  = tid & 15;
    const int ty  = tid >> 4;

    float acc[8][4];
#pragma unroll
    for (int i = 0; i < 8; i++)
#pragma unroll
        for (int j = 0; j < 4; j++) acc[i][j] = 0.f;

    for (int k0 = 0; k0 < Cc; k0 += 16) {
#pragma unroll
        for (int j = 0; j < 8; j++) {
            int c = ak + j * 2;
            As[c][am] = xb[(size_t)(k0 + c) * WH + am];
        }
        *(float4*)&Bs[bkr][bn4] =
            *(const float4*)&Wx[(size_t)(k0 + bkr) * Gg + bn + bn4];
        __syncthreads();
#pragma unroll
        for (int kk = 0; kk < 16; kk++) {
            float4 a0 = *(float4*)&As[kk][ty * 8];
            float4 a1 = *(float4*)&As[kk][ty * 8 + 4];
            float4 bv = *(float4*)&Bs[kk][tx * 4];
            float aa[8] = {a0.x, a0.y, a0.z, a0.w, a1.x, a1.y, a1.z, a1.w};
            float bb[4] = {bv.x, bv.y, bv.z, bv.w};
#pragma unroll
            for (int i = 0; i < 8; i++)
#pragma unroll
                for (int j = 0; j < 4; j++) acc[i][j] += aa[i] * bb[j];
        }
        __syncthreads();
    }

    float4 bb4 = *(const float4*)&bias[bn + tx * 4];
#pragma unroll
    for (int i = 0; i < 8; i++) {
        int m = bm + ty * 8 + i;
        float4 v;
        v.x = acc[i][0] + bb4.x;
        v.y = acc[i][1] + bb4.y;
        v.z = acc[i][2] + bb4.z;
        v.w = acc[i][3] + bb4.w;
        *(float4*)&g_xp[(size_t)m * Gg + bn + tx * 4] = v;
    }
}

// ---------------- grid-wide software barrier (all blocks co-resident) ----------------
__device__ __forceinline__ void gsync() {
    __threadfence();
    __syncthreads();
    if (threadIdx.x == 0) {
        unsigned old = *(volatile unsigned*)&g_gen;
        if (atomicAdd(&g_cnt, 1u) == NBLK - 1) {
            g_cnt = 0;
            __threadfence();
            *(volatile unsigned*)&g_gen = old + 1;
        } else {
            while (*(volatile unsigned*)&g_gen == old) { }
        }
        __threadfence();
    }
    __syncthreads();
}

// ---------------- persistent fused MD-LSTM recurrence ----------------
// Block bid: nb = bid&15 (16 hid cols), rg = bid>>4 (row group, 9 groups).
// SMEM-resident weight slice Ws[512][80]: Ws[kk][g*16+t] = Wh(kk)[g*256+nb*16+t].
// Per diagonal: rows [rg*mt2, +mt2), mt2=ceil(M/9)<=29. 256 thr = 16 tn x 16 tm.
// Row-pairs P=ceil(mt2/2); K split across S=16/P tm-slices when rows are few.
__global__ __launch_bounds__(256, 1) void mdlstm_persist(const float* __restrict__ Wh1,
                                                         const float* __restrict__ Wh2) {
    extern __shared__ float sm[];
    float* Ws = sm;
    float* Asm = sm + WS_FLOATS;
    const float** pls = (const float**)(sm + WS_FLOATS + AS_FLOATS);
    const float** pus = pls + 32;

    const int tid = threadIdx.x;
    const int bid = blockIdx.x;
    const int nb  = bid & 15;
    const int rg  = bid >> 4;

    // one-time weight preload (coalesced-ish 64B runs)
    for (int i = tid; i < WS_FLOATS; i += 256) {
        int kk = i / 80, c = i - kk * 80;
        int g = c >> 4, t = c & 15;
        int col = g * 256 + nb * 16 + t;
        Ws[i] = (kk < 256) ? Wh1[(size_t)kk * Gg + col]
                           : Wh2[(size_t)(kk - 256) * Gg + col];
    }

    const int tn = tid & 15;
    const int tm = tid >> 4;
    const int srow = tid >> 3;        // staging: row 0..31
    const int skq  = (tid & 7) * 8;   // staging: 8 consecutive k

    for (int d = 0; d < NDIAG; d++) {
        int w_lo = d - (Hd - 1); if (w_lo < 0) w_lo = 0;
        int w_hi = (d < Wd - 1) ? d : (Wd - 1);
        int M = (w_hi - w_lo + 1) * Bk;
        int mt2 = (M + RG - 1) / RG;
        int r0 = rg * mt2;

        if (r0 < M) {
            // K-split schedule
            int P = (mt2 + 1) >> 1;
            int S = 1;
            while (2 * S * P <= 16 && S < 8) S <<= 1;
            int pair = tm % P;
            int slice = tm / P;
            bool active = (slice < S);
            int cw = 8 / S;                    // chunks per slice
            int c_lo = active ? slice * cw : 0;
            int c_hi = active ? c_lo + cw : 0;

            // neighbor pointers
            if (tid < 32) {
                const float* pl = nullptr;
                const float* pu = nullptr;
                int gr = r0 + tid;
                if (tid < mt2 && gr < M) {
                    int ci = gr >> 3, b = gr & 7;
                    int w = w_lo + ci, h = d - w;
                    if (h > 0) pl = g_h + ((size_t)((w * Hd + (h - 1)) * Bk + b)) * HIDd;
                    if (w > 0) pu = g_h + ((size_t)(((w - 1) * Hd + h) * Bk + b)) * HIDd;
                }
                pls[tid] = pl;
                pus[tid] = pu;
            }
            __syncthreads();   // ptrs ready (also covers Ws preload at d==0)

            float acc[2][5];
#pragma unroll
            for (int i = 0; i < 2; i++)
#pragma unroll
                for (int g = 0; g < 5; g++) acc[i][g] = 0.f;

            // stage chunk 0 into buffer 0
            {
                const float* p = pls[srow];
                float4 v0 = {0,0,0,0}, v1 = {0,0,0,0};
                if (p) { v0 = *(const float4*)(p + skq); v1 = *(const float4*)(p + skq + 4); }
                float* Ab = Asm;
                Ab[(skq+0)*AS_PITCH + srow] = v0.x; Ab[(skq+1)*AS_PITCH + srow] = v0.y;
                Ab[(skq+2)*AS_PITCH + srow] = v0.z; Ab[(skq+3)*AS_PITCH + srow] = v0.w;
                Ab[(skq+4)*AS_PITCH + srow] = v1.x; Ab[(skq+5)*AS_PITCH + srow] = v1.y;
                Ab[(skq+6)*AS_PITCH + srow] = v1.z; Ab[(skq+7)*AS_PITCH + srow] = v1.w;
            }
            __syncthreads();

            for (int c = 0; c < 8; c++) {
                // prefetch chunk c+1 into regs
                float4 v0 = {0,0,0,0}, v1 = {0,0,0,0};
                if (c < 7) {
                    const float* p = (c + 1 < 4) ? pls[srow] : pus[srow];
                    int koff = ((c + 1) & 3) * 64 + skq;
                    if (p) { v0 = *(const float4*)(p + koff); v1 = *(const float4*)(p + koff + 4); }
                }
                // compute this chunk if in my K-slice
                if (active && c >= c_lo && c < c_hi) {
                    const float* Acur = Asm + (c & 1) * AS_BUF;
#pragma unroll 16
                    for (int kk = 0; kk < 64; kk++) {
                        float2 a = *(const float2*)&Acur[kk * AS_PITCH + 2 * pair];
                        const float* wrow = Ws + (c * 64 + kk) * 80;
                        float b0 = wrow[tn];
                        float b1 = wrow[16 + tn];
                        float b2 = wrow[32 + tn];
                        float b3 = wrow[48 + tn];
                        float b4 = wrow[64 + tn];
                        acc[0][0] += a.x * b0; acc[0][1] += a.x * b1; acc[0][2] += a.x * b2;
                        acc[0][3] += a.x * b3; acc[0][4] += a.x * b4;
                        acc[1][0] += a.y * b0; acc[1][1] += a.y * b1; acc[1][2] += a.y * b2;
                        acc[1][3] += a.y * b3; acc[1][4] += a.y * b4;
                    }
                }
                if (c < 7) {
                    float* Ab = Asm + ((c + 1) & 1) * AS_BUF;
                    Ab[(skq+0)*AS_PITCH + srow] = v0.x; Ab[(skq+1)*AS_PITCH + srow] = v0.y;
                    Ab[(skq+2)*AS_PITCH + srow] = v0.z; Ab[(skq+3)*AS_PITCH + srow] = v0.w;
                    Ab[(skq+4)*AS_PITCH + srow] = v1.x; Ab[(skq+5)*AS_PITCH + srow] = v1.y;
                    Ab[(skq+6)*AS_PITCH + srow] = v1.z; Ab[(skq+7)*AS_PITCH + srow] = v1.w;
                    __syncthreads();
                }
            }

            // cross-slice reduction (reuse A buffers)
            if (S > 1) {
                __syncthreads();
                float* red = Asm;
                if (active && slice > 0) {
                    float* dst = red + ((slice - 1) * P + pair) * 160 + tn;
#pragma unroll
                    for (int i = 0; i < 2; i++)
#pragma unroll
                        for (int g = 0; g < 5; g++) dst[(i * 5 + g) * 16] = acc[i][g];
                }
                __syncthreads();
                if (slice == 0) {
                    for (int s = 1; s < S; s++) {
                        const float* src = red + ((s - 1) * P + pair) * 160 + tn;
#pragma unroll
                        for (int i = 0; i < 2; i++)
#pragma unroll
                            for (int g = 0; g < 5; g++) acc[i][g] += src[(i * 5 + g) * 16];
                    }
                }
            }

            // fused LSTM pointwise (slice-0 threads own full rows)
            if (slice == 0) {
                const int hid = nb * 16 + tn;
#pragma unroll
                for (int i = 0; i < 2; i++) {
                    int lr = 2 * pair + i;
                    int gr = r0 + lr;
                    if (lr < mt2 && gr < M) {
                        int ci = gr >> 3, b = gr & 7;
                        int w = w_lo + ci, h = d - w;

                        const float* xg = g_xp + ((size_t)(b * WH + w * Hd + h)) * Gg;
                        float gi  = acc[i][0] + xg[hid];
                        float gf1 = acc[i][1] + xg[HIDd + hid];
                        float gf2 = acc[i][2] + xg[2 * HIDd + hid];
                        float go  = acc[i][3] + xg[3 * HIDd + hid];
                        float gc  = acc[i][4] + xg[4 * HIDd + hid];

                        float i_ = 1.f / (1.f + expf(-gi));
                        float f1 = 1.f / (1.f + expf(-gf1));
                        float f2 = 1.f / (1.f + expf(-gf2));
                        float o_ = 1.f / (1.f + expf(-go));
                        float cand = tanhf(gc);

                        float cl = (h > 0) ? g_c[((size_t)((w * Hd + (h - 1)) * Bk + b)) * HIDd + hid] : 0.f;
                        float cu = (w > 0) ? g_c[((size_t)(((w - 1) * Hd + h) * Bk + b)) * HIDd + hid] : 0.f;

                        float cc = i_ * cand + f1 * cl + f2 * cu;
                        float hv = o_ * tanhf(cc);

                        size_t oidx = ((size_t)((w * Hd + h) * Bk + b)) * HIDd + hid;
                        g_c[oidx] = cc;
                        g_h[oidx] = hv;
                    }
                }
            }
        }

        gsync();
    }
}

// ---------------- BN stats ----------------
__global__ __launch_bounds__(256) void bn_reduce1() {
    const int t = threadIdx.x;
    const size_t r0 = (size_t)blockIdx.x * 128;
    float s = 0.f, s2 = 0.f;
    for (int r = 0; r < 128; r++) {
        float v = g_h[(r0 + r) * HIDd + t];
        s += v;
        s2 += v * v;
    }
    g_part[blockIdx.x * HIDd + t] = s;
    g_part[128 * HIDd + blockIdx.x * HIDd + t] = s2;
}

__global__ __launch_bounds__(256) void bn_reduce2(const float* __restrict__ gamma,
                                                  const float* __restrict__ beta) {
    const int t = threadIdx.x;
    float s = 0.f, s2 = 0.f;
    for (int i = 0; i < 128; i++) {
        s += g_part[i * HIDd + t];
        s2 += g_part[128 * HIDd + i * HIDd + t];
    }
    const float invn = 1.f / (float)MXP;
    float mean = s * invn;
    float var  = s2 * invn - mean * mean;
    float sc   = gamma[t] * rsqrtf(var + 1e-5f);
    g_scale[t] = sc;
    g_shift[t] = beta[t] - mean * sc;
}

// ---------------- final writeout ----------------
__global__ __launch_bounds__(256) void writeout(float* __restrict__ out) {
    size_t idx = (size_t)blockIdx.x * 256 + threadIdx.x;
    int hh = (int)(idx & 31);
    int w  = (int)((idx >> 5) & 63);
    int ch = (int)((idx >> 11) & 255);
    int b  = (int)(idx >> 19);
    size_t src = ((size_t)((w * Hd + hh) * Bk + b)) * HIDd + ch;
    float st = g_h[src];
    float cc = g_c[src];
    out[idx]                          = tanhf(st * g_scale[ch] + g_shift[ch]);
    out[(size_t)MXP * HIDd + idx]     = st;
    out[(size_t)2 * MXP * HIDd + idx] = cc;
}

// ---------------- launch ----------------
extern "C" void kernel_launch(void* const* d_in, const int* in_sizes, int n_in,
                              void* d_out, int out_size) {
    const float* x     = (const float*)d_in[0];
    const float* Wx    = (const float*)d_in[1];
    const float* Wh1   = (const float*)d_in[2];
    const float* Wh2   = (const float*)d_in[3];
    const float* bias  = (const float*)d_in[4];
    const float* gamma = (const float*)d_in[5];
    const float* beta  = (const float*)d_in[6];
    float* out = (float*)d_out;

    cudaFuncSetAttribute(mdlstm_persist,
                         cudaFuncAttributeMaxDynamicSharedMemorySize, SMEM_BYTES);

    xp_gemm<<<dim3(Gg / 64, MXP / 128), 256>>>(x, Wx, bias);
    mdlstm_persist<<<NBLK, 256, SMEM_BYTES>>>(Wh1, Wh2);
    bn_reduce1<<<128, 256>>>();
    bn_reduce2<<<1, 256>>>(gamma, beta);
    writeout<<<MXP, 256>>>(out);
}